// round 14
// baseline (speedup 1.0000x reference)
#include <cuda_runtime.h>
#include <math.h>

// Problem constants
#define PB     32
#define PN     325
#define PK     20
#define S_IN   12
#define S_OUT  12
#define PC     10
#define H48    48
#define BN     (PB * PN)                 // 10400 nodes
#define OUT_DATA_ELEMS (BN * PC * S_OUT) // 1,248,000

#define NODES_PER_CTA  16
#define MAIN_THREADS   160               // 5 warps; phase1: 2 units/thread (16*20/160)
#define MAIN_CTAS      (BN / NODES_PER_CTA)   // 650
#define ROWF           28                // padded row stride in floats (112B)

// ---------------- scratch (no allocation allowed) ----------------
__device__ __align__(16) float  g_wh [BN * S_OUT];   // wh per node (12)
__device__ __align__(16) float  g_hxb[BN * H48];     // hx + a1_b per node (48)
__device__ double g_acc[3];        // 0: cluster-loss sum, 1: dist sum, 2: wh sum
__device__ unsigned int g_done;    // last-block counter (self-resetting)

__device__ __forceinline__ float leaky(float x) { return x >= 0.f ? x : 0.5f * x; }

// ---- packed f32x2 helpers ----
typedef unsigned long long u64q;
__device__ __forceinline__ u64q pk2(float a, float b) {
    u64q r; asm("mov.b64 %0,{%1,%2};" : "=l"(r) : "f"(a), "f"(b)); return r;
}
__device__ __forceinline__ void upk2(u64q v, float& a, float& b) {
    asm("mov.b64 {%0,%1},%2;" : "=f"(a), "=f"(b) : "l"(v));
}
__device__ __forceinline__ u64q fma2(u64q a, u64q b, u64q c) {
    u64q d; asm("fma.rn.f32x2 %0,%1,%2,%3;" : "=l"(d) : "l"(a), "l"(b), "l"(c)); return d;
}

// ---------------- kernel 1: per-node precompute (wh + hx) ----------------
__global__ void __launch_bounds__(128)
k_pre(const float* __restrict__ in,
      const float* __restrict__ wW,  const float* __restrict__ wb,
      const float* __restrict__ a1W, const float* __restrict__ a1b)
{
    __shared__ float s_wW[S_IN * S_OUT];
    __shared__ float s_wb[S_OUT];
    __shared__ float s_a1W[S_OUT * H48];     // first half only (hx)
    __shared__ float s_a1b[H48];
    __shared__ double s_red[4];

    for (int i = threadIdx.x; i < S_IN * S_OUT; i += 128) s_wW[i]  = wW[i];
    if (threadIdx.x < S_OUT) s_wb[threadIdx.x] = wb[threadIdx.x];
    for (int i = threadIdx.x; i < S_OUT * H48;  i += 128) s_a1W[i] = a1W[i];
    if (threadIdx.x < H48) s_a1b[threadIdx.x] = a1b[threadIdx.x];
    __syncthreads();

    const int t    = threadIdx.x;
    const int node = blockIdx.x * 64 + (t >> 1);
    const int half = t & 1;
    float whsum = 0.f;

    if (node < BN) {
        const float4* xp = reinterpret_cast<const float4*>(&in[node * S_IN]);
        float4 x0 = xp[0], x1 = xp[1], x2 = xp[2];
        float x[S_IN] = {x0.x, x0.y, x0.z, x0.w, x1.x, x1.y, x1.z, x1.w,
                         x2.x, x2.y, x2.z, x2.w};

        float wh[S_OUT];
        #pragma unroll
        for (int j = 0; j < S_OUT; j++) {
            float a = s_wb[j];
            #pragma unroll
            for (int i = 0; i < S_IN; i++) a = fmaf(x[i], s_wW[i * S_OUT + j], a);
            wh[j] = leaky(a);
        }
        if (half == 0) {
            float4* wp = reinterpret_cast<float4*>(&g_wh[(size_t)node * S_OUT]);
            wp[0] = make_float4(wh[0], wh[1], wh[2], wh[3]);
            wp[1] = make_float4(wh[4], wh[5], wh[6], wh[7]);
            wp[2] = make_float4(wh[8], wh[9], wh[10], wh[11]);
            #pragma unroll
            for (int j = 0; j < S_OUT; j++) whsum += wh[j];
        }

        const int d0 = half * 24;
        #pragma unroll
        for (int dq = 0; dq < 24; dq += 4) {
            float hx[4];
            #pragma unroll
            for (int q = 0; q < 4; q++) {
                int d = d0 + dq + q;
                float a = s_a1b[d];
                #pragma unroll
                for (int j = 0; j < S_OUT; j++)
                    a = fmaf(wh[j], s_a1W[j * H48 + d], a);
                hx[q] = a;
            }
            *reinterpret_cast<float4*>(&g_hxb[(size_t)node * H48 + d0 + dq]) =
                make_float4(hx[0], hx[1], hx[2], hx[3]);
        }
    }

    #pragma unroll
    for (int o = 16; o > 0; o >>= 1) whsum += __shfl_down_sync(0xffffffffu, whsum, o);
    int warp = threadIdx.x >> 5, lane = threadIdx.x & 31;
    if (lane == 0) s_red[warp] = (double)whsum;
    __syncthreads();
    if (threadIdx.x == 0)
        atomicAdd(&g_acc[2], s_red[0] + s_red[1] + s_red[2] + s_red[3]);
}

// ---------------- kernel 2: main ----------------
// Phase 1: thread -> 2 (node,k) units (same k, nodes nl and nl+8); hy recomputed.
// Row layout per (node,k): [0:12) wtn, [12:22) am, [22] nrm, [23:28) pad.
// Phase 2: warp-per-node kk-loop; row kk broadcast, lane rows register-resident.
__global__ void __launch_bounds__(MAIN_THREADS, 4)
k_main(const int* __restrict__ idx,
       const float* __restrict__ a1W,
       const float* __restrict__ a2W, const float* __restrict__ a2b,
       float* __restrict__ out)
{
    __shared__ __align__(16) float s_rows[NODES_PER_CTA][PK][ROWF];  // 35.8 KB
    __shared__ __align__(16) float s_wd[H48][24];   // [0:12) a1W[12:] col d, [12:22) a2W row d
    __shared__ float  s_b2[PC];
    __shared__ float4 s_hx4[NODES_PER_CTA * 12];
    __shared__ double s_redc[5], s_redd[5];

    const int tid  = threadIdx.x;
    const int wid  = tid >> 5;
    const int lane = tid & 31;

    // ---- stage interleaved weights + bias + hx rows ----
    for (int i = tid; i < H48 * 24; i += MAIN_THREADS) {
        int d = i / 24, j = i - d * 24;
        float v = 0.f;
        if (j < 12)      v = a1W[(S_OUT + j) * H48 + d];
        else if (j < 22) v = a2W[d * PC + (j - 12)];
        s_wd[d][j] = v;
    }
    if (tid < PC) s_b2[tid] = a2b[tid];
    for (int i = tid; i < NODES_PER_CTA * 12; i += MAIN_THREADS) {
        int n = i / 12, q = i - n * 12;
        s_hx4[i] = reinterpret_cast<const float4*>(
            g_hxb + (size_t)(blockIdx.x * NODES_PER_CTA + n) * H48)[q];
    }
    __syncthreads();

    // ================= phase 1: 2 units per thread =================
    {
        const int k   = tid % PK;
        const int nl0 = tid / PK;          // 0..7
        const int nl1 = nl0 + 8;           // 8..15
        const int node0 = blockIdx.x * NODES_PER_CTA + nl0;
        const int node1 = node0 + 8;
        const int jn0 = (node0 / PN) * PN + idx[node0 * PK + k];
        const int jn1 = (node1 / PN) * PN + idx[node1 * PK + k];

        // gather both neighbor wh rows
        const float4* wp0 = reinterpret_cast<const float4*>(&g_wh[(size_t)jn0 * S_OUT]);
        const float4* wp1 = reinterpret_cast<const float4*>(&g_wh[(size_t)jn1 * S_OUT]);
        float4 a0 = wp0[0], a1v = wp0[1], a2v = wp0[2];
        float4 b0 = wp1[0], b1v = wp1[1], b2v = wp1[2];

        // norms; store wtn + nrm rows now (frees nothing logically but fills smem early)
        float n20 = a0.x*a0.x + a0.y*a0.y + a0.z*a0.z + a0.w*a0.w
                  + a1v.x*a1v.x + a1v.y*a1v.y + a1v.z*a1v.z + a1v.w*a1v.w
                  + a2v.x*a2v.x + a2v.y*a2v.y + a2v.z*a2v.z + a2v.w*a2v.w;
        float n21 = b0.x*b0.x + b0.y*b0.y + b0.z*b0.z + b0.w*b0.w
                  + b1v.x*b1v.x + b1v.y*b1v.y + b1v.z*b1v.z + b1v.w*b1v.w
                  + b2v.x*b2v.x + b2v.y*b2v.y + b2v.z*b2v.z + b2v.w*b2v.w;
        const float nrm0 = sqrtf(n20) + 1e-8f, inv0 = 1.f / nrm0;
        const float nrm1 = sqrtf(n21) + 1e-8f, inv1 = 1.f / nrm1;
        {
            float4* r0 = reinterpret_cast<float4*>(&s_rows[nl0][k][0]);
            r0[0] = make_float4(a0.x*inv0, a0.y*inv0, a0.z*inv0, a0.w*inv0);
            r0[1] = make_float4(a1v.x*inv0, a1v.y*inv0, a1v.z*inv0, a1v.w*inv0);
            r0[2] = make_float4(a2v.x*inv0, a2v.y*inv0, a2v.z*inv0, a2v.w*inv0);
            float4* r1 = reinterpret_cast<float4*>(&s_rows[nl1][k][0]);
            r1[0] = make_float4(b0.x*inv1, b0.y*inv1, b0.z*inv1, b0.w*inv1);
            r1[1] = make_float4(b1v.x*inv1, b1v.y*inv1, b1v.z*inv1, b1v.w*inv1);
            r1[2] = make_float4(b2v.x*inv1, b2v.y*inv1, b2v.z*inv1, b2v.w*inv1);
        }

        // packed wh registers for hy recompute
        u64q whp0[6] = { pk2(a0.x, a0.y), pk2(a0.z, a0.w), pk2(a1v.x, a1v.y),
                         pk2(a1v.z, a1v.w), pk2(a2v.x, a2v.y), pk2(a2v.z, a2v.w) };
        u64q whp1[6] = { pk2(b0.x, b0.y), pk2(b0.z, b0.w), pk2(b1v.x, b1v.y),
                         pk2(b1v.z, b1v.w), pk2(b2v.x, b2v.y), pk2(b2v.z, b2v.w) };

        u64q acc0[5] = { pk2(s_b2[0], s_b2[1]), pk2(s_b2[2], s_b2[3]),
                         pk2(s_b2[4], s_b2[5]), pk2(s_b2[6], s_b2[7]),
                         pk2(s_b2[8], s_b2[9]) };
        u64q acc1[5]; 
        #pragma unroll
        for (int c = 0; c < 5; c++) acc1[c] = acc0[c];
        const u64q zero2 = pk2(0.f, 0.f);

        #pragma unroll
        for (int ch = 0; ch < 12; ch++) {
            float4 hxa = s_hx4[nl0 * 12 + ch];
            float4 hxb = s_hx4[nl1 * 12 + ch];
            float ha[4] = { hxa.x, hxa.y, hxa.z, hxa.w };
            float hb[4] = { hxb.x, hxb.y, hxb.z, hxb.w };
            #pragma unroll
            for (int q = 0; q < 4; q++) {
                const int d = ch * 4 + q;
                const float4* wr = reinterpret_cast<const float4*>(&s_wd[d][0]);
                float4 y0 = wr[0], y1 = wr[1], y2 = wr[2];
                float4 c0 = wr[3], c1 = wr[4], c2 = wr[5];
                // weight pairs packed once, reused for both units
                u64q yp0 = pk2(y0.x, y0.y), yp1 = pk2(y0.z, y0.w), yp2 = pk2(y1.x, y1.y);
                u64q yp3 = pk2(y1.z, y1.w), yp4 = pk2(y2.x, y2.y), yp5 = pk2(y2.z, y2.w);
                u64q hs0 = fma2(whp0[0], yp0, zero2);
                u64q hs1 = fma2(whp1[0], yp0, zero2);
                hs0 = fma2(whp0[1], yp1, hs0); hs1 = fma2(whp1[1], yp1, hs1);
                hs0 = fma2(whp0[2], yp2, hs0); hs1 = fma2(whp1[2], yp2, hs1);
                hs0 = fma2(whp0[3], yp3, hs0); hs1 = fma2(whp1[3], yp3, hs1);
                hs0 = fma2(whp0[4], yp4, hs0); hs1 = fma2(whp1[4], yp4, hs1);
                hs0 = fma2(whp0[5], yp5, hs0); hs1 = fma2(whp1[5], yp5, hs1);
                float l0, h0, l1, h1;
                upk2(hs0, l0, h0); upk2(hs1, l1, h1);
                const float hv0 = leaky(ha[q] + (l0 + h0));
                const float hv1 = leaky(hb[q] + (l1 + h1));
                const u64q hh0 = pk2(hv0, hv0), hh1 = pk2(hv1, hv1);
                u64q ap0 = pk2(c0.x, c0.y), ap1 = pk2(c0.z, c0.w), ap2 = pk2(c1.x, c1.y);
                u64q ap3 = pk2(c1.z, c1.w), ap4 = pk2(c2.x, c2.y);
                acc0[0] = fma2(hh0, ap0, acc0[0]); acc1[0] = fma2(hh1, ap0, acc1[0]);
                acc0[1] = fma2(hh0, ap1, acc0[1]); acc1[1] = fma2(hh1, ap1, acc1[1]);
                acc0[2] = fma2(hh0, ap2, acc0[2]); acc1[2] = fma2(hh1, ap2, acc1[2]);
                acc0[3] = fma2(hh0, ap3, acc0[3]); acc1[3] = fma2(hh1, ap3, acc1[3]);
                acc0[4] = fma2(hh0, ap4, acc0[4]); acc1[4] = fma2(hh1, ap4, acc1[4]);
            }
        }

        // softmax both units, store am + nrm
        #pragma unroll
        for (int u = 0; u < 2; u++) {
            float av[PC];
            u64q* acc = u ? acc1 : acc0;
            upk2(acc[0], av[0], av[1]); upk2(acc[1], av[2], av[3]);
            upk2(acc[2], av[4], av[5]); upk2(acc[3], av[6], av[7]);
            upk2(acc[4], av[8], av[9]);
            float m = -1e30f;
            #pragma unroll
            for (int c = 0; c < PC; c++) { av[c] = leaky(av[c]); m = fmaxf(m, av[c]); }
            float sum = 0.f;
            #pragma unroll
            for (int c = 0; c < PC; c++) { av[c] = __expf(av[c] - m); sum += av[c]; }
            const float is = 1.f / sum;
            #pragma unroll
            for (int c = 0; c < PC; c++) av[c] *= is;
            const int nl = u ? nl1 : nl0;
            const float nr = u ? nrm1 : nrm0;
            float4* r = reinterpret_cast<float4*>(&s_rows[nl][k][12]);
            r[0] = make_float4(av[0], av[1], av[2], av[3]);
            r[1] = make_float4(av[4], av[5], av[6], av[7]);
            r[2] = make_float4(av[8], av[9], nr, 0.f);
        }
    }
    __syncthreads();

    // ================= phase 2: warp-per-node kk loop =================
    double clsum = 0.0, dsum = 0.0;
    const int ll   = (lane < PK) ? lane : (PK - 1);
    const bool act = (lane < PK);
    const int oc   = lane >> 1;          // output c (0..9 for lanes<20)
    const int oh   = lane & 1;           // output half

    for (int nl = wid; nl < NODES_PER_CTA; nl += 5) {
        const int node = blockIdx.x * NODES_PER_CTA + nl;

        // lane's own row -> registers
        const float4* lr = reinterpret_cast<const float4*>(&s_rows[nl][ll][0]);
        float4 r0 = lr[0], r1 = lr[1], r2 = lr[2], r3 = lr[3], r4 = lr[4], r5 = lr[5];

        float o0 = 0.f, o1 = 0.f, o2 = 0.f, o3 = 0.f, o4 = 0.f, o5 = 0.f;
        float fds = 0.f, fcl = 0.f;

        #pragma unroll 4
        for (int kk = 0; kk < PK; kk++) {
            const float4* br = reinterpret_cast<const float4*>(&s_rows[nl][kk][0]);  // uniform
            float4 c0 = br[0], c1 = br[1], c2 = br[2], c3 = br[3], c4 = br[4], c5 = br[5];

            // dist: wtn dot (12)
            float dist = r0.x * c0.x;
            dist = fmaf(r0.y, c0.y, dist); dist = fmaf(r0.z, c0.z, dist);
            dist = fmaf(r0.w, c0.w, dist); dist = fmaf(r1.x, c1.x, dist);
            dist = fmaf(r1.y, c1.y, dist); dist = fmaf(r1.z, c1.z, dist);
            dist = fmaf(r1.w, c1.w, dist); dist = fmaf(r2.x, c2.x, dist);
            dist = fmaf(r2.y, c2.y, dist); dist = fmaf(r2.z, c2.z, dist);
            dist = fmaf(r2.w, c2.w, dist);
            // prob: am dot (10)
            float prob = r3.x * c3.x;
            prob = fmaf(r3.y, c3.y, prob); prob = fmaf(r3.z, c3.z, prob);
            prob = fmaf(r3.w, c3.w, prob); prob = fmaf(r4.x, c4.x, prob);
            prob = fmaf(r4.y, c4.y, prob); prob = fmaf(r4.z, c4.z, prob);
            prob = fmaf(r4.w, c4.w, prob); prob = fmaf(r5.x, c5.x, prob);
            prob = fmaf(r5.y, c5.y, prob);

            if (act) {
                fds += dist;
                if (ll != kk) {
                    float pcl = fminf(fmaxf(prob, 1e-4f), 1.f - 1e-4f);
                    const float lg = __logf(pcl);
                    fcl += (dist >= 0.5f) ? -lg : lg;
                }
                // output: am[kk][oc] * nrm[kk] * wtn[kk][oh*6 + i]
                const float amk = s_rows[nl][kk][12 + oc] * c5.z;   // scalar LDS + mul
                const float w0s = oh ? c1.z : c0.x;
                const float w1s = oh ? c1.w : c0.y;
                const float w2s = oh ? c2.x : c0.z;
                const float w3s = oh ? c2.y : c0.w;
                const float w4s = oh ? c2.z : c1.x;
                const float w5s = oh ? c2.w : c1.y;
                o0 = fmaf(amk, w0s, o0); o1 = fmaf(amk, w1s, o1);
                o2 = fmaf(amk, w2s, o2); o3 = fmaf(amk, w3s, o3);
                o4 = fmaf(amk, w4s, o4); o5 = fmaf(amk, w5s, o5);
            }
        }

        if (act) {
            float* op = out + (size_t)node * (PC * S_OUT) + oc * S_OUT + oh * 6;
            *reinterpret_cast<float2*>(op + 0) = make_float2(o0, o1);
            *reinterpret_cast<float2*>(op + 2) = make_float2(o2, o3);
            *reinterpret_cast<float2*>(op + 4) = make_float2(o4, o5);
            clsum += (double)fcl;
            dsum  += (double)fds;
        }
    }

    // ---- reduce: warp -> block -> global atomics; last CTA finalizes ----
    #pragma unroll
    for (int o = 16; o > 0; o >>= 1) {
        clsum += __shfl_down_sync(0xffffffffu, clsum, o);
        dsum  += __shfl_down_sync(0xffffffffu, dsum,  o);
    }
    if (lane == 0) { s_redc[wid] = clsum; s_redd[wid] = dsum; }
    __syncthreads();

    if (tid == 0) {
        double tc = 0.0, td = 0.0;
        #pragma unroll
        for (int q = 0; q < 5; q++) { tc += s_redc[q]; td += s_redd[q]; }
        atomicAdd(&g_acc[0], tc);
        atomicAdd(&g_acc[1], td);
        __threadfence();
        unsigned int done = atomicAdd(&g_done, 1u);
        if (done == (unsigned int)(gridDim.x - 1)) {
            __threadfence();
            volatile double* acc = g_acc;
            double c0 = acc[0], c1 = acc[1], c2 = acc[2];
            out[OUT_DATA_ELEMS + 0] = (float)(c0 / (double)BN);
            out[OUT_DATA_ELEMS + 1] = (float)(c1 / ((double)BN * PK * PK));
            out[OUT_DATA_ELEMS + 2] = (float)(c2 / ((double)BN * S_OUT));
            acc[0] = 0.0; acc[1] = 0.0; acc[2] = 0.0;
            g_done = 0;
            __threadfence();
        }
    }
}

// ---------------- launch ----------------
extern "C" void kernel_launch(void* const* d_in, const int* in_sizes, int n_in,
                              void* d_out, int out_size)
{
    const float* input_data = (const float*)d_in[1];
    const float* wW  = (const float*)d_in[2];
    const float* wb  = (const float*)d_in[3];
    const float* a1W = (const float*)d_in[4];
    const float* a1b = (const float*)d_in[5];
    const float* a2W = (const float*)d_in[6];
    const float* a2b = (const float*)d_in[7];
    const int*   idx = (const int*)d_in[8];
    float* out = (float*)d_out;

    k_pre <<<(BN + 63) / 64, 128>>>(input_data, wW, wb, a1W, a1b);
    k_main<<<MAIN_CTAS, MAIN_THREADS>>>(idx, a1W, a2W, a2b, out);
}

// round 17
// speedup vs baseline: 1.2025x; 1.2025x over previous
#include <cuda_runtime.h>
#include <math.h>

// Problem constants
#define PB     32
#define PN     325
#define PK     20
#define S_IN   12
#define S_OUT  12
#define PC     10
#define H48    48
#define BN     (PB * PN)                 // 10400 nodes
#define OUT_DATA_ELEMS (BN * PC * S_OUT) // 1,248,000

#define NODES_PER_CTA  8
#define MAIN_THREADS   160               // 5 warps; 8*20 units in phase 1
#define MAIN_CTAS      (BN / NODES_PER_CTA)   // 1300
#define ROWF           28                // padded row stride (112B)

// ---------------- scratch (no allocation allowed) ----------------
__device__ __align__(16) float  g_wh [BN * S_OUT];   // wh per node (12)
__device__ __align__(16) float  g_hxb[BN * H48];     // hx + a1_b per node (48)
__device__ double g_acc[3];        // 0: cluster-loss sum, 1: dist sum, 2: wh sum
__device__ unsigned int g_done;    // last-block counter (self-resetting)

__device__ __forceinline__ float leaky(float x) { return x >= 0.f ? x : 0.5f * x; }

// ---- packed f32x2 helpers ----
typedef unsigned long long u64q;
__device__ __forceinline__ u64q pk2(float a, float b) {
    u64q r; asm("mov.b64 %0,{%1,%2};" : "=l"(r) : "f"(a), "f"(b)); return r;
}
__device__ __forceinline__ void upk2(u64q v, float& a, float& b) {
    asm("mov.b64 {%0,%1},%2;" : "=f"(a), "=f"(b) : "l"(v));
}
__device__ __forceinline__ u64q fma2(u64q a, u64q b, u64q c) {
    u64q d; asm("fma.rn.f32x2 %0,%1,%2,%3;" : "=l"(d) : "l"(a), "l"(b), "l"(c)); return d;
}

// ---------------- kernel 1: per-node precompute (wh + hx) ----------------
__global__ void __launch_bounds__(128)
k_pre(const float* __restrict__ in,
      const float* __restrict__ wW,  const float* __restrict__ wb,
      const float* __restrict__ a1W, const float* __restrict__ a1b)
{
    __shared__ float s_wW[S_IN * S_OUT];
    __shared__ float s_wb[S_OUT];
    __shared__ float s_a1W[S_OUT * H48];     // first half only (hx)
    __shared__ float s_a1b[H48];
    __shared__ double s_red[4];

    for (int i = threadIdx.x; i < S_IN * S_OUT; i += 128) s_wW[i]  = wW[i];
    if (threadIdx.x < S_OUT) s_wb[threadIdx.x] = wb[threadIdx.x];
    for (int i = threadIdx.x; i < S_OUT * H48;  i += 128) s_a1W[i] = a1W[i];
    if (threadIdx.x < H48) s_a1b[threadIdx.x] = a1b[threadIdx.x];
    __syncthreads();

    const int t    = threadIdx.x;
    const int node = blockIdx.x * 64 + (t >> 1);
    const int half = t & 1;
    float whsum = 0.f;

    if (node < BN) {
        const float4* xp = reinterpret_cast<const float4*>(&in[node * S_IN]);
        float4 x0 = xp[0], x1 = xp[1], x2 = xp[2];
        float x[S_IN] = {x0.x, x0.y, x0.z, x0.w, x1.x, x1.y, x1.z, x1.w,
                         x2.x, x2.y, x2.z, x2.w};

        float wh[S_OUT];
        #pragma unroll
        for (int j = 0; j < S_OUT; j++) {
            float a = s_wb[j];
            #pragma unroll
            for (int i = 0; i < S_IN; i++) a = fmaf(x[i], s_wW[i * S_OUT + j], a);
            wh[j] = leaky(a);
        }
        if (half == 0) {
            float4* wp = reinterpret_cast<float4*>(&g_wh[(size_t)node * S_OUT]);
            wp[0] = make_float4(wh[0], wh[1], wh[2], wh[3]);
            wp[1] = make_float4(wh[4], wh[5], wh[6], wh[7]);
            wp[2] = make_float4(wh[8], wh[9], wh[10], wh[11]);
            #pragma unroll
            for (int j = 0; j < S_OUT; j++) whsum += wh[j];
        }

        const int d0 = half * 24;
        #pragma unroll
        for (int dq = 0; dq < 24; dq += 4) {
            float hx[4];
            #pragma unroll
            for (int q = 0; q < 4; q++) {
                int d = d0 + dq + q;
                float a = s_a1b[d];
                #pragma unroll
                for (int j = 0; j < S_OUT; j++)
                    a = fmaf(wh[j], s_a1W[j * H48 + d], a);
                hx[q] = a;
            }
            *reinterpret_cast<float4*>(&g_hxb[(size_t)node * H48 + d0 + dq]) =
                make_float4(hx[0], hx[1], hx[2], hx[3]);
        }
    }

    #pragma unroll
    for (int o = 16; o > 0; o >>= 1) whsum += __shfl_down_sync(0xffffffffu, whsum, o);
    int warp = threadIdx.x >> 5, lane = threadIdx.x & 31;
    if (lane == 0) s_red[warp] = (double)whsum;
    __syncthreads();
    if (threadIdx.x == 0)
        atomicAdd(&g_acc[2], s_red[0] + s_red[1] + s_red[2] + s_red[3]);
}

// ---------------- kernel 2: main ----------------
// Phase 1 (R12 style): thread -> one (node,k) unit; hy recomputed from gathered wh.
// Row layout per (node,k): [0:12) wtn (normalized), [12:22) am, [22] nrm, [23:28) pad.
// Phase 2 (R14 style): warp-per-node kk loop; row kk broadcast-loaded, lane row in regs.
__global__ void __launch_bounds__(MAIN_THREADS, 5)
k_main(const int* __restrict__ idx,
       const float* __restrict__ a1W,
       const float* __restrict__ a2W, const float* __restrict__ a2b,
       float* __restrict__ out)
{
    __shared__ __align__(16) float s_rows[NODES_PER_CTA][PK][ROWF];  // 17.9 KB
    __shared__ __align__(16) float s_wd[H48][24];  // [0:12) a1W[12:] col d, [12:22) a2W row d
    __shared__ float  s_b2[PC];
    __shared__ float4 s_hx4[NODES_PER_CTA * 12];
    __shared__ double s_redc[5], s_redd[5];

    const int tid  = threadIdx.x;
    const int wid  = tid >> 5;
    const int lane = tid & 31;

    // ---- stage interleaved weights + bias + hx rows ----
    for (int i = tid; i < H48 * 24; i += MAIN_THREADS) {
        int d = i / 24, j = i - d * 24;
        float v = 0.f;
        if (j < 12)      v = a1W[(S_OUT + j) * H48 + d];
        else if (j < 22) v = a2W[d * PC + (j - 12)];
        s_wd[d][j] = v;
    }
    if (tid < PC) s_b2[tid] = a2b[tid];
    for (int i = tid; i < NODES_PER_CTA * 12; i += MAIN_THREADS) {
        int n = i / 12, q = i - n * 12;
        s_hx4[i] = reinterpret_cast<const float4*>(
            g_hxb + (size_t)(blockIdx.x * NODES_PER_CTA + n) * H48)[q];
    }
    __syncthreads();

    // ================= phase 1: one thread = one (node,k) unit =================
    {
        const int nl   = tid / PK;           // 0..7
        const int k    = tid - nl * PK;      // 0..19
        const int node = blockIdx.x * NODES_PER_CTA + nl;
        const int jn   = (node / PN) * PN + idx[node * PK + k];

        // gather neighbor wh (only gather in the kernel): 3 LDG.128
        const float4* wp = reinterpret_cast<const float4*>(&g_wh[(size_t)jn * S_OUT]);
        float4 wa = wp[0], wbv = wp[1], wc = wp[2];

        // norm; store normalized wtn row
        float n2 = wa.x * wa.x;
        n2 = fmaf(wa.y, wa.y, n2); n2 = fmaf(wa.z, wa.z, n2); n2 = fmaf(wa.w, wa.w, n2);
        n2 = fmaf(wbv.x, wbv.x, n2); n2 = fmaf(wbv.y, wbv.y, n2); n2 = fmaf(wbv.z, wbv.z, n2);
        n2 = fmaf(wbv.w, wbv.w, n2); n2 = fmaf(wc.x, wc.x, n2); n2 = fmaf(wc.y, wc.y, n2);
        n2 = fmaf(wc.z, wc.z, n2); n2 = fmaf(wc.w, wc.w, n2);
        const float nrm = sqrtf(n2) + 1e-8f;
        const float inv = 1.f / nrm;
        {
            float4* r = reinterpret_cast<float4*>(&s_rows[nl][k][0]);
            r[0] = make_float4(wa.x * inv, wa.y * inv, wa.z * inv, wa.w * inv);
            r[1] = make_float4(wbv.x * inv, wbv.y * inv, wbv.z * inv, wbv.w * inv);
            r[2] = make_float4(wc.x * inv, wc.y * inv, wc.z * inv, wc.w * inv);
        }

        // packed wh for hy recompute
        u64q whp[6] = { pk2(wa.x, wa.y), pk2(wa.z, wa.w),
                        pk2(wbv.x, wbv.y), pk2(wbv.z, wbv.w),
                        pk2(wc.x, wc.y), pk2(wc.z, wc.w) };

        u64q acc[5] = { pk2(s_b2[0], s_b2[1]), pk2(s_b2[2], s_b2[3]),
                        pk2(s_b2[4], s_b2[5]), pk2(s_b2[6], s_b2[7]),
                        pk2(s_b2[8], s_b2[9]) };
        const u64q zero2 = pk2(0.f, 0.f);

        #pragma unroll
        for (int ch = 0; ch < 12; ch++) {
            float4 hx4 = s_hx4[nl * 12 + ch];
            float hxv[4] = { hx4.x, hx4.y, hx4.z, hx4.w };
            #pragma unroll
            for (int q = 0; q < 4; q++) {
                const int d = ch * 4 + q;
                const float4* wr = reinterpret_cast<const float4*>(&s_wd[d][0]);  // uniform
                float4 y0 = wr[0], y1 = wr[1], y2 = wr[2];
                float4 c0 = wr[3], c1 = wr[4], c2 = wr[5];
                u64q hs = fma2(whp[0], pk2(y0.x, y0.y), zero2);
                hs = fma2(whp[1], pk2(y0.z, y0.w), hs);
                hs = fma2(whp[2], pk2(y1.x, y1.y), hs);
                hs = fma2(whp[3], pk2(y1.z, y1.w), hs);
                hs = fma2(whp[4], pk2(y2.x, y2.y), hs);
                hs = fma2(whp[5], pk2(y2.z, y2.w), hs);
                float hlo, hhi; upk2(hs, hlo, hhi);
                const float h = leaky(hxv[q] + (hlo + hhi));
                const u64q hh = pk2(h, h);
                acc[0] = fma2(hh, pk2(c0.x, c0.y), acc[0]);
                acc[1] = fma2(hh, pk2(c0.z, c0.w), acc[1]);
                acc[2] = fma2(hh, pk2(c1.x, c1.y), acc[2]);
                acc[3] = fma2(hh, pk2(c1.z, c1.w), acc[3]);
                acc[4] = fma2(hh, pk2(c2.x, c2.y), acc[4]);
            }
        }

        // leaky + softmax; store am + nrm
        float av[PC];
        upk2(acc[0], av[0], av[1]); upk2(acc[1], av[2], av[3]);
        upk2(acc[2], av[4], av[5]); upk2(acc[3], av[6], av[7]);
        upk2(acc[4], av[8], av[9]);
        float m = -1e30f;
        #pragma unroll
        for (int c = 0; c < PC; c++) { av[c] = leaky(av[c]); m = fmaxf(m, av[c]); }
        float sum = 0.f;
        #pragma unroll
        for (int c = 0; c < PC; c++) { av[c] = __expf(av[c] - m); sum += av[c]; }
        const float is = 1.f / sum;
        #pragma unroll
        for (int c = 0; c < PC; c++) av[c] *= is;

        float4* r = reinterpret_cast<float4*>(&s_rows[nl][k][12]);
        r[0] = make_float4(av[0], av[1], av[2], av[3]);
        r[1] = make_float4(av[4], av[5], av[6], av[7]);
        r[2] = make_float4(av[8], av[9], nrm, 0.f);
    }
    __syncthreads();

    // ================= phase 2: warp-per-node kk loop (broadcast rows) =================
    double clsum = 0.0, dsum = 0.0;
    const int  ll  = (lane < PK) ? lane : (PK - 1);
    const bool act = (lane < PK);
    const int  oc  = lane >> 1;          // output c (0..9 for lanes<20)
    const int  oh  = lane & 1;           // output half

    for (int nl = wid; nl < NODES_PER_CTA; nl += 5) {
        const int node = blockIdx.x * NODES_PER_CTA + nl;

        // lane's own row -> registers (scattered, once per node)
        const float4* lr = reinterpret_cast<const float4*>(&s_rows[nl][ll][0]);
        float4 r0 = lr[0], r1 = lr[1], r2 = lr[2], r3 = lr[3], r4 = lr[4], r5 = lr[5];

        float o0 = 0.f, o1 = 0.f, o2 = 0.f, o3 = 0.f, o4 = 0.f, o5 = 0.f;
        float fds = 0.f, fcl = 0.f;

        #pragma unroll 4
        for (int kk = 0; kk < PK; kk++) {
            const float4* br = reinterpret_cast<const float4*>(&s_rows[nl][kk][0]);  // uniform
            float4 c0 = br[0], c1 = br[1], c2 = br[2], c3 = br[3], c4 = br[4], c5 = br[5];

            // dist: wtn dot (12)
            float dist = r0.x * c0.x;
            dist = fmaf(r0.y, c0.y, dist); dist = fmaf(r0.z, c0.z, dist);
            dist = fmaf(r0.w, c0.w, dist); dist = fmaf(r1.x, c1.x, dist);
            dist = fmaf(r1.y, c1.y, dist); dist = fmaf(r1.z, c1.z, dist);
            dist = fmaf(r1.w, c1.w, dist); dist = fmaf(r2.x, c2.x, dist);
            dist = fmaf(r2.y, c2.y, dist); dist = fmaf(r2.z, c2.z, dist);
            dist = fmaf(r2.w, c2.w, dist);
            // prob: am dot (10)
            float prob = r3.x * c3.x;
            prob = fmaf(r3.y, c3.y, prob); prob = fmaf(r3.z, c3.z, prob);
            prob = fmaf(r3.w, c3.w, prob); prob = fmaf(r4.x, c4.x, prob);
            prob = fmaf(r4.y, c4.y, prob); prob = fmaf(r4.z, c4.z, prob);
            prob = fmaf(r4.w, c4.w, prob); prob = fmaf(r5.x, c5.x, prob);
            prob = fmaf(r5.y, c5.y, prob);

            if (act) {
                fds += dist;
                if (ll != kk) {
                    float pcl = fminf(fmaxf(prob, 1e-4f), 1.f - 1e-4f);
                    const float lg = __logf(pcl);
                    fcl += (dist >= 0.5f) ? -lg : lg;
                }
                // output: am[kk][oc] * nrm[kk] * wtn[kk][oh*6 + i]
                const float amk = s_rows[nl][kk][12 + oc] * c5.z;
                const float w0s = oh ? c1.z : c0.x;
                const float w1s = oh ? c1.w : c0.y;
                const float w2s = oh ? c2.x : c0.z;
                const float w3s = oh ? c2.y : c0.w;
                const float w4s = oh ? c2.z : c1.x;
                const float w5s = oh ? c2.w : c1.y;
                o0 = fmaf(amk, w0s, o0); o1 = fmaf(amk, w1s, o1);
                o2 = fmaf(amk, w2s, o2); o3 = fmaf(amk, w3s, o3);
                o4 = fmaf(amk, w4s, o4); o5 = fmaf(amk, w5s, o5);
            }
        }

        if (act) {
            float* op = out + (size_t)node * (PC * S_OUT) + oc * S_OUT + oh * 6;
            *reinterpret_cast<float2*>(op + 0) = make_float2(o0, o1);
            *reinterpret_cast<float2*>(op + 2) = make_float2(o2, o3);
            *reinterpret_cast<float2*>(op + 4) = make_float2(o4, o5);
            clsum += (double)fcl;
            dsum  += (double)fds;
        }
    }

    // ---- reduce: warp -> block -> global atomics; last CTA finalizes ----
    #pragma unroll
    for (int o = 16; o > 0; o >>= 1) {
        clsum += __shfl_down_sync(0xffffffffu, clsum, o);
        dsum  += __shfl_down_sync(0xffffffffu, dsum,  o);
    }
    if (lane == 0) { s_redc[wid] = clsum; s_redd[wid] = dsum; }
    __syncthreads();

    if (tid == 0) {
        double tc = 0.0, td = 0.0;
        #pragma unroll
        for (int q = 0; q < 5; q++) { tc += s_redc[q]; td += s_redd[q]; }
        atomicAdd(&g_acc[0], tc);
        atomicAdd(&g_acc[1], td);
        __threadfence();
        unsigned int done = atomicAdd(&g_done, 1u);
        if (done == (unsigned int)(gridDim.x - 1)) {
            __threadfence();
            volatile double* acc = g_acc;
            double c0 = acc[0], c1 = acc[1], c2 = acc[2];
            out[OUT_DATA_ELEMS + 0] = (float)(c0 / (double)BN);
            out[OUT_DATA_ELEMS + 1] = (float)(c1 / ((double)BN * PK * PK));
            out[OUT_DATA_ELEMS + 2] = (float)(c2 / ((double)BN * S_OUT));
            acc[0] = 0.0; acc[1] = 0.0; acc[2] = 0.0;
            g_done = 0;
            __threadfence();
        }
    }
}

// ---------------- launch ----------------
extern "C" void kernel_launch(void* const* d_in, const int* in_sizes, int n_in,
                              void* d_out, int out_size)
{
    const float* input_data = (const float*)d_in[1];
    const float* wW  = (const float*)d_in[2];
    const float* wb  = (const float*)d_in[3];
    const float* a1W = (const float*)d_in[4];
    const float* a1b = (const float*)d_in[5];
    const float* a2W = (const float*)d_in[6];
    const float* a2b = (const float*)d_in[7];
    const int*   idx = (const int*)d_in[8];
    float* out = (float*)d_out;

    k_pre <<<(BN + 63) / 64, 128>>>(input_data, wW, wb, a1W, a1b);
    k_main<<<MAIN_CTAS, MAIN_THREADS>>>(idx, a1W, a2W, a2b, out);
}